// round 7
// baseline (speedup 1.0000x reference)
#include <cuda_runtime.h>
#include <stdint.h>

#define N_NODES 50000
#define D       128
#define EH      500000
#define ES      250000
#define NCLS    47
#define E_TOT   (2 * (EH + ES))

typedef unsigned long long ull;

// ---------------- scratch (device globals; no runtime allocation) ----------------
__device__ int   g_cnt[4 * N_NODES];
__device__ int   g_off[4 * (N_NODES + 1)];
__device__ int   g_cur[4 * N_NODES];
__device__ int   g_eidx[E_TOT];
__device__ float g_neigh[N_NODES * D];
__device__ float g_H1[N_NODES * D];
__device__ float g_Hd[N_NODES * D];

__device__ __forceinline__ int eidx_base(int p) {
    return p == 0 ? 0 : p == 1 ? EH : p == 2 ? (EH + ES) : (2 * EH + ES);
}

// ---------------- f32x2 packed math helpers ----------------
__device__ __forceinline__ ull fma2(ull a, ull b, ull c) {
    ull d;
    asm("fma.rn.f32x2 %0, %1, %2, %3;" : "=l"(d) : "l"(a), "l"(b), "l"(c));
    return d;
}
__device__ __forceinline__ ull packf2(float x, float y) {
    ull d;
    asm("mov.b64 %0, {%1, %2};" : "=l"(d) : "f"(x), "f"(y));
    return d;
}
__device__ __forceinline__ void unpackf2(ull v, float& x, float& y) {
    asm("mov.b64 {%0, %1}, %2;" : "=f"(x), "=f"(y) : "l"(v));
}

// ---------------- CSR build (fused) ----------------
__global__ void count_all_kernel(const int* __restrict__ hd0, const int* __restrict__ sd0,
                                 const int* __restrict__ hd1, const int* __restrict__ sd1) {
    int i = blockIdx.x * blockDim.x + threadIdx.x;
    if (i >= E_TOT) return;
    int pair, off;
    const int* p;
    if (i < EH)               { pair = 0; p = hd0; off = i; }
    else if (i < EH + ES)     { pair = 1; p = sd0; off = i - EH; }
    else if (i < 2 * EH + ES) { pair = 2; p = hd1; off = i - EH - ES; }
    else                      { pair = 3; p = sd1; off = i - 2 * EH - ES; }
    atomicAdd(&g_cnt[pair * N_NODES + __ldg(p + off)], 1);
}

__global__ void scan_kernel() {
    const int p = blockIdx.x;
    int* cnt = g_cnt + p * N_NODES;
    int* off = g_off + p * (N_NODES + 1);
    int* cur = g_cur + p * N_NODES;
    const int T = 1024;
    const int C = (N_NODES + T - 1) / T;
    __shared__ int part[T];
    int t = threadIdx.x;
    int base = t * C;
    int s = 0;
#pragma unroll 1
    for (int i = 0; i < C; i++) {
        int j = base + i;
        if (j < N_NODES) s += cnt[j];
    }
    part[t] = s;
    __syncthreads();
    for (int d2 = 1; d2 < T; d2 <<= 1) {
        int v = (t >= d2) ? part[t - d2] : 0;
        __syncthreads();
        part[t] += v;
        __syncthreads();
    }
    int run = part[t] - s;
#pragma unroll 1
    for (int i = 0; i < C; i++) {
        int j = base + i;
        if (j < N_NODES) {
            off[j] = run;
            cur[j] = run;
            run += cnt[j];
        }
    }
    if (t == T - 1) off[N_NODES] = part[t];
}

__global__ void bucket_all_kernel(const int* __restrict__ hs0, const int* __restrict__ hd0,
                                  const int* __restrict__ ss0, const int* __restrict__ sd0,
                                  const int* __restrict__ hs1, const int* __restrict__ hd1,
                                  const int* __restrict__ ss1, const int* __restrict__ sd1) {
    int i = blockIdx.x * blockDim.x + threadIdx.x;
    if (i >= E_TOT) return;
    int pair, off;
    const int *ps, *pd;
    if (i < EH)               { pair = 0; ps = hs0; pd = hd0; off = i; }
    else if (i < EH + ES)     { pair = 1; ps = ss0; pd = sd0; off = i - EH; }
    else if (i < 2 * EH + ES) { pair = 2; ps = hs1; pd = hd1; off = i - EH - ES; }
    else                      { pair = 3; ps = ss1; pd = sd1; off = i - 2 * EH - ES; }
    int d = __ldg(pd + off);
    int pos = atomicAdd(&g_cur[pair * N_NODES + d], 1);
    g_eidx[eidx_base(pair) + pos] = __ldg(ps + off);
}

// ---------------- Hdelta = H - HBar ----------------
template <int LAYER>
__global__ void hdelta_kernel(const float* __restrict__ Hext, const float* __restrict__ hbar) {
    int i = blockIdx.x * blockDim.x + threadIdx.x;
    if (i >= N_NODES * D / 4) return;
    const float4* H4 = (LAYER == 0) ? (const float4*)Hext : (const float4*)g_H1;
    float4 a = __ldg(H4 + i);
    float4 b = __ldg((const float4*)hbar + i);
    ((float4*)g_Hd)[i] = make_float4(a.x - b.x, a.y - b.y, a.z - b.z, a.w - b.w);
}

// ---------------- per-node gather (warp-collective, MLP=4) ----------------
__device__ __forceinline__ void acc_add(float4& a, float4 v) {
    a.x += v.x; a.y += v.y; a.z += v.z; a.w += v.w;
}

__device__ __forceinline__ void gather_node(int w, int lane,
                                            const int* __restrict__ offH,
                                            const int* __restrict__ offD,
                                            const int* __restrict__ idxH,
                                            const int* __restrict__ idxD,
                                            const float* __restrict__ hbar) {
    int h0 = __ldg(offH + w), h1 = __ldg(offH + w + 1);
    int d0 = __ldg(offD + w), d1 = __ldg(offD + w + 1);

    float4 a0 = make_float4(0,0,0,0), a1 = a0, a2 = a0, a3 = a0;
    int e = h0;
    for (; e + 4 <= h1; e += 4) {
        int i0 = __ldg(idxH + e + 0), i1 = __ldg(idxH + e + 1);
        int i2 = __ldg(idxH + e + 2), i3 = __ldg(idxH + e + 3);
        float4 v0 = __ldg((const float4*)(hbar + (size_t)i0 * D) + lane);
        float4 v1 = __ldg((const float4*)(hbar + (size_t)i1 * D) + lane);
        float4 v2 = __ldg((const float4*)(hbar + (size_t)i2 * D) + lane);
        float4 v3 = __ldg((const float4*)(hbar + (size_t)i3 * D) + lane);
        acc_add(a0, v0); acc_add(a1, v1); acc_add(a2, v2); acc_add(a3, v3);
    }
    for (; e < h1; e++) {
        int s = __ldg(idxH + e);
        acc_add(a0, __ldg((const float4*)(hbar + (size_t)s * D) + lane));
    }
    acc_add(a0, a1); acc_add(a2, a3); acc_add(a0, a2);
    float invh = 1.f / fmaxf((float)(h1 - h0), 1.f);
    float4 o = make_float4(a0.x * invh, a0.y * invh, a0.z * invh, a0.w * invh);

    float4 b0 = make_float4(0,0,0,0), b1 = b0, b2 = b0, b3 = b0;
    e = d0;
    for (; e + 4 <= d1; e += 4) {
        int i0 = __ldg(idxD + e + 0), i1 = __ldg(idxD + e + 1);
        int i2 = __ldg(idxD + e + 2), i3 = __ldg(idxD + e + 3);
        float4 v0 = __ldg((const float4*)(g_Hd + (size_t)i0 * D) + lane);
        float4 v1 = __ldg((const float4*)(g_Hd + (size_t)i1 * D) + lane);
        float4 v2 = __ldg((const float4*)(g_Hd + (size_t)i2 * D) + lane);
        float4 v3 = __ldg((const float4*)(g_Hd + (size_t)i3 * D) + lane);
        acc_add(b0, v0); acc_add(b1, v1); acc_add(b2, v2); acc_add(b3, v3);
    }
    for (; e < d1; e++) {
        int s = __ldg(idxD + e);
        acc_add(b0, __ldg((const float4*)(g_Hd + (size_t)s * D) + lane));
    }
    acc_add(b0, b1); acc_add(b2, b3); acc_add(b0, b2);
    float invd = 1.f / fmaxf((float)(d1 - d0), 1.f);
    o.x += b0.x * invd; o.y += b0.y * invd;
    o.z += b0.z * invd; o.w += b0.w * invd;

    *(float4*)(g_neigh + (size_t)w * D + lane * 4) = o;
}

// ---------------- fused layer: agg (phase A) + GEMM+bias+ReLU (phase B) ----------------
// Block owns BM=64 rows. Phase A: 8 warps x 8 nodes gather -> g_neigh (own rows only).
// Phase B: tiled GEMM  out[r][n] = relu(b[n] + sum_k [H|g_neigh][r][k] * W[n][k]).
template <int LAYER, int DOUT, int BN, int HPAIR, int DPAIR, int MAXB>
__global__ void __launch_bounds__(256, MAXB)
fused_layer_kernel(const float* __restrict__ Hext,
                   const float* __restrict__ hbar,
                   const float* __restrict__ W,
                   const float* __restrict__ bias,
                   float* __restrict__ outext) {
    constexpr int BM = 64, BK = 32, K = 2 * D, NK = K / BK;
    constexpr int TM = 4;
    constexpr int TN = BN / 16;
    constexpr int TNP = TN / 2;
    constexpr int NA = (BM * BK) / (256 * 4);
    constexpr int NB = (BN * BK) / (256 * 4);
    constexpr int APAD = BM + 4;
    constexpr int BPAD = BN + 4;

    const float* H = (LAYER == 0) ? Hext : g_H1;
    float* out     = (LAYER == 0) ? g_H1 : outext;

    __shared__ float As[BK][APAD];
    __shared__ float Bs[BK][BPAD];

    const int t    = threadIdx.x;
    const int row0 = blockIdx.x * BM;
    const int warp = t >> 5;
    const int lane = t & 31;

    // ================= phase A: aggregate this block's rows =================
    {
        const int* offH = g_off + HPAIR * (N_NODES + 1);
        const int* offD = g_off + DPAIR * (N_NODES + 1);
        const int* idxH = g_eidx + eidx_base(HPAIR);
        const int* idxD = g_eidx + eidx_base(DPAIR);
#pragma unroll 1
        for (int i = 0; i < BM / 8; i++) {           // 8 nodes per warp
            int node = row0 + warp * (BM / 8) + i;
            if (node < N_NODES)
                gather_node(node, lane, offH, offD, idxH, idxD, hbar);
        }
    }
    __syncthreads();   // g_neigh rows for this block visible to all its threads

    // ================= phase B: GEMM =================
    const int tx = t & 15;
    const int ty = t >> 4;

    float4 pa[NA], pb[NB];

    auto load_tile = [&](int kit) {
        const int k0 = kit * BK;
        const bool useH = (k0 < D);
        const float* Asrc = useH ? (H + k0) : (g_neigh + (k0 - D));
#pragma unroll
        for (int v = 0; v < NA; v++) {
            int id = v * 256 + t;
            int m  = id >> 3;
            int kq = id & 7;
            int r  = min(row0 + m, N_NODES - 1);
            // plain load for neigh (written by this block this kernel); __ldg ok for H
            pa[v] = useH ? __ldg((const float4*)(Asrc + (size_t)r * D) + kq)
                         : *((const float4*)(Asrc + (size_t)r * D) + kq);
        }
#pragma unroll
        for (int v = 0; v < NB; v++) {
            int id = v * 256 + t;
            int n  = id >> 3;
            int kq = id & 7;
            pb[v] = (n < DOUT) ? __ldg((const float4*)(W + n * K + k0) + kq)
                               : make_float4(0.f, 0.f, 0.f, 0.f);
        }
    };
    auto store_tile = [&]() {
#pragma unroll
        for (int v = 0; v < NA; v++) {
            int id = v * 256 + t;
            int m  = id >> 3;
            int kq = id & 7;
            int col = (((m >> 2) ^ (kq >> 1)) << 2) + (m & 3);
            As[(kq << 2) + 0][col] = pa[v].x;
            As[(kq << 2) + 1][col] = pa[v].y;
            As[(kq << 2) + 2][col] = pa[v].z;
            As[(kq << 2) + 3][col] = pa[v].w;
        }
#pragma unroll
        for (int v = 0; v < NB; v++) {
            int id = v * 256 + t;
            int n  = id >> 3;
            int kq = id & 7;
            int col = (((n >> 2) ^ (kq >> 1)) << 2) + (n & 3);
            Bs[(kq << 2) + 0][col] = pb[v].x;
            Bs[(kq << 2) + 1][col] = pb[v].y;
            Bs[(kq << 2) + 2][col] = pb[v].z;
            Bs[(kq << 2) + 3][col] = pb[v].w;
        }
    };

    ull acc2[TM][TNP];
#pragma unroll
    for (int i = 0; i < TM; i++)
#pragma unroll
        for (int p = 0; p < TNP; p++) acc2[i][p] = 0ULL;

    load_tile(0);

    for (int kit = 0; kit < NK; kit++) {
        store_tile();
        __syncthreads();
        if (kit + 1 < NK) load_tile(kit + 1);

#pragma unroll
        for (int kk = 0; kk < BK; kk++) {
            const int s = (kk >> 3) & 3;
            ull ad[TM];
            {
                int gA = ty ^ s;                     // TM=4: one float4 group
                float4 a = *(const float4*)&As[kk][gA << 2];
                ad[0] = packf2(a.x, a.x);
                ad[1] = packf2(a.y, a.y);
                ad[2] = packf2(a.z, a.z);
                ad[3] = packf2(a.w, a.w);
            }
            ull bp[TNP];
#pragma unroll
            for (int u = 0; u < TN / 4; u++) {
                int gB = (tx * (TN / 4) + u) ^ s;
                ulonglong2 bb = *(const ulonglong2*)&Bs[kk][gB << 2];
                bp[2 * u + 0] = bb.x;
                bp[2 * u + 1] = bb.y;
            }
#pragma unroll
            for (int i = 0; i < TM; i++)
#pragma unroll
                for (int p = 0; p < TNP; p++)
                    acc2[i][p] = fma2(ad[i], bp[p], acc2[i][p]);
        }
        __syncthreads();
    }

    // ---- epilogue ----
    float bn[TN];
#pragma unroll
    for (int j = 0; j < TN; j++) {
        int n = tx * TN + j;
        bn[j] = (n < DOUT) ? __ldg(bias + n) : 0.f;
    }
#pragma unroll
    for (int i = 0; i < TM; i++) {
        int r = row0 + ty * TM + i;
        if (r >= N_NODES) continue;
        float res[TN];
#pragma unroll
        for (int p = 0; p < TNP; p++) {
            float lo, hi;
            unpackf2(acc2[i][p], lo, hi);
            res[2 * p + 0] = fmaxf(lo + bn[2 * p + 0], 0.f);
            res[2 * p + 1] = fmaxf(hi + bn[2 * p + 1], 0.f);
        }
        if (DOUT == BN) {
#pragma unroll
            for (int u = 0; u < TN / 4; u++) {
                float4 o = make_float4(res[4 * u], res[4 * u + 1],
                                       res[4 * u + 2], res[4 * u + 3]);
                *(float4*)(out + (size_t)r * DOUT + tx * TN + 4 * u) = o;
            }
        } else {
#pragma unroll
            for (int j = 0; j < TN; j++) {
                int n = tx * TN + j;
                if (n < DOUT) out[(size_t)r * DOUT + n] = res[j];
            }
        }
    }
}

// ---------------- launch ----------------
extern "C" void kernel_launch(void* const* d_in, const int* in_sizes, int n_in,
                              void* d_out, int out_size) {
    const float* x     = (const float*)d_in[0];
    const float* hbar0 = (const float*)d_in[1];
    const float* hbar1 = (const float*)d_in[2];
    const float* W0    = (const float*)d_in[3];
    const float* b0    = (const float*)d_in[4];
    const float* W1    = (const float*)d_in[5];
    const float* b1    = (const float*)d_in[6];
    const int* hsrc0   = (const int*)d_in[7];
    const int* hdst0   = (const int*)d_in[8];
    const int* ssrc0   = (const int*)d_in[9];
    const int* sdst0   = (const int*)d_in[10];
    const int* hsrc1   = (const int*)d_in[11];
    const int* hdst1   = (const int*)d_in[12];
    const int* ssrc1   = (const int*)d_in[13];
    const int* sdst1   = (const int*)d_in[14];
    float* out = (float*)d_out;

    const int GE  = (E_TOT + 255) / 256;
    const int GEL = (N_NODES * D / 4 + 255) / 256;
    const int GL  = (N_NODES + 63) / 64;        // 782 fused blocks

    // ---- CSR build ----
    void* cnt_ptr = nullptr;
    cudaGetSymbolAddress(&cnt_ptr, g_cnt);
    cudaMemsetAsync(cnt_ptr, 0, sizeof(int) * 4 * N_NODES);
    count_all_kernel<<<GE, 256>>>(hdst0, sdst0, hdst1, sdst1);
    scan_kernel<<<4, 1024>>>();
    bucket_all_kernel<<<GE, 256>>>(hsrc0, hdst0, ssrc0, sdst0,
                                   hsrc1, hdst1, ssrc1, sdst1);

    // ---- layer 0 ----
    hdelta_kernel<0><<<GEL, 256>>>(x, hbar0);
    fused_layer_kernel<0, 128, 128, 0, 1, 2><<<GL, 256>>>(x, hbar0, W0, b0, nullptr);

    // ---- layer 1 ----
    hdelta_kernel<1><<<GEL, 256>>>(nullptr, hbar1);
    fused_layer_kernel<1, NCLS, 64, 2, 3, 3><<<GL, 256>>>(nullptr, hbar1, W1, b1, out);
}

// round 8
// speedup vs baseline: 1.0918x; 1.0918x over previous
#include <cuda_runtime.h>
#include <stdint.h>

#define N_NODES 50000
#define D       128
#define EH      500000
#define ES      250000
#define NCLS    47
#define E_TOT   (2 * (EH + ES))

typedef unsigned long long ull;

// ---------------- scratch (device globals; no runtime allocation) ----------------
__device__ int   g_cnt[4 * N_NODES];
__device__ int   g_off[4 * (N_NODES + 1)];
__device__ int   g_cur[4 * N_NODES];
__device__ int   g_eidx[E_TOT];
__device__ float g_neigh[N_NODES * D];
__device__ float g_H1[N_NODES * D];
__device__ float g_Hd[N_NODES * D];

__device__ __forceinline__ int eidx_base(int p) {
    return p == 0 ? 0 : p == 1 ? EH : p == 2 ? (EH + ES) : (2 * EH + ES);
}

// ---------------- f32x2 packed math helpers ----------------
__device__ __forceinline__ ull fma2(ull a, ull b, ull c) {
    ull d;
    asm("fma.rn.f32x2 %0, %1, %2, %3;" : "=l"(d) : "l"(a), "l"(b), "l"(c));
    return d;
}
__device__ __forceinline__ ull packf2(float x, float y) {
    ull d;
    asm("mov.b64 %0, {%1, %2};" : "=l"(d) : "f"(x), "f"(y));
    return d;
}
__device__ __forceinline__ void unpackf2(ull v, float& x, float& y) {
    asm("mov.b64 {%0, %1}, %2;" : "=f"(x), "=f"(y) : "l"(v));
}

// ---------------- CSR build (fused) ----------------
__global__ void count_all_kernel(const int* __restrict__ hd0, const int* __restrict__ sd0,
                                 const int* __restrict__ hd1, const int* __restrict__ sd1) {
    int i = blockIdx.x * blockDim.x + threadIdx.x;
    if (i >= E_TOT) return;
    int pair, off;
    const int* p;
    if (i < EH)               { pair = 0; p = hd0; off = i; }
    else if (i < EH + ES)     { pair = 1; p = sd0; off = i - EH; }
    else if (i < 2 * EH + ES) { pair = 2; p = hd1; off = i - EH - ES; }
    else                      { pair = 3; p = sd1; off = i - 2 * EH - ES; }
    atomicAdd(&g_cnt[pair * N_NODES + __ldg(p + off)], 1);
}

__global__ void scan_kernel() {
    const int p = blockIdx.x;
    int* cnt = g_cnt + p * N_NODES;
    int* off = g_off + p * (N_NODES + 1);
    int* cur = g_cur + p * N_NODES;
    const int T = 1024;
    const int C = (N_NODES + T - 1) / T;
    __shared__ int part[T];
    int t = threadIdx.x;
    int base = t * C;
    int s = 0;
#pragma unroll 1
    for (int i = 0; i < C; i++) {
        int j = base + i;
        if (j < N_NODES) s += cnt[j];
    }
    part[t] = s;
    __syncthreads();
    for (int d2 = 1; d2 < T; d2 <<= 1) {
        int v = (t >= d2) ? part[t - d2] : 0;
        __syncthreads();
        part[t] += v;
        __syncthreads();
    }
    int run = part[t] - s;
#pragma unroll 1
    for (int i = 0; i < C; i++) {
        int j = base + i;
        if (j < N_NODES) {
            off[j] = run;
            cur[j] = run;
            run += cnt[j];
        }
    }
    if (t == T - 1) off[N_NODES] = part[t];
}

__global__ void bucket_all_kernel(const int* __restrict__ hs0, const int* __restrict__ hd0,
                                  const int* __restrict__ ss0, const int* __restrict__ sd0,
                                  const int* __restrict__ hs1, const int* __restrict__ hd1,
                                  const int* __restrict__ ss1, const int* __restrict__ sd1) {
    int i = blockIdx.x * blockDim.x + threadIdx.x;
    if (i >= E_TOT) return;
    int pair, off;
    const int *ps, *pd;
    if (i < EH)               { pair = 0; ps = hs0; pd = hd0; off = i; }
    else if (i < EH + ES)     { pair = 1; ps = ss0; pd = sd0; off = i - EH; }
    else if (i < 2 * EH + ES) { pair = 2; ps = hs1; pd = hd1; off = i - EH - ES; }
    else                      { pair = 3; ps = ss1; pd = sd1; off = i - 2 * EH - ES; }
    int d = __ldg(pd + off);
    int pos = atomicAdd(&g_cur[pair * N_NODES + d], 1);
    g_eidx[eidx_base(pair) + pos] = __ldg(ps + off);
}

// ---------------- Hdelta = H - HBar ----------------
template <int LAYER>
__global__ void hdelta_kernel(const float* __restrict__ Hext, const float* __restrict__ hbar) {
    int i = blockIdx.x * blockDim.x + threadIdx.x;
    if (i >= N_NODES * D / 4) return;
    const float4* H4 = (LAYER == 0) ? (const float4*)Hext : (const float4*)g_H1;
    float4 a = __ldg(H4 + i);
    float4 b = __ldg((const float4*)hbar + i);
    ((float4*)g_Hd)[i] = make_float4(a.x - b.x, a.y - b.y, a.z - b.z, a.w - b.w);
}

// ---------------- aggregation: 2 warps per node, balanced list split ----------------
__device__ __forceinline__ void acc_add(float4& a, float4 v) {
    a.x += v.x; a.y += v.y; a.z += v.z; a.w += v.w;
}

__device__ __forceinline__ float4 gather_range(const float* __restrict__ feat,
                                               const int* __restrict__ idx,
                                               int ea, int eb, int lane) {
    float4 a0 = make_float4(0,0,0,0), a1 = a0, a2 = a0, a3 = a0;
    int e = ea;
    for (; e + 4 <= eb; e += 4) {
        int i0 = __ldg(idx + e + 0), i1 = __ldg(idx + e + 1);
        int i2 = __ldg(idx + e + 2), i3 = __ldg(idx + e + 3);
        float4 v0 = __ldg((const float4*)(feat + (size_t)i0 * D) + lane);
        float4 v1 = __ldg((const float4*)(feat + (size_t)i1 * D) + lane);
        float4 v2 = __ldg((const float4*)(feat + (size_t)i2 * D) + lane);
        float4 v3 = __ldg((const float4*)(feat + (size_t)i3 * D) + lane);
        acc_add(a0, v0); acc_add(a1, v1); acc_add(a2, v2); acc_add(a3, v3);
    }
    for (; e < eb; e++) {
        int s = __ldg(idx + e);
        acc_add(a0, __ldg((const float4*)(feat + (size_t)s * D) + lane));
    }
    acc_add(a0, a1); acc_add(a2, a3); acc_add(a0, a2);
    return a0;
}

// 256 threads = 8 warps = 4 nodes/block (N_NODES % 4 == 0 -> no divergence).
// Warp pair (2j, 2j+1): each warp gathers HALF of the hist list and HALF of the
// delta list for node j. Odd warp dumps partials to smem; even warp combines.
template <int HPAIR, int DPAIR>
__global__ void __launch_bounds__(256)
agg_split_kernel(const float* __restrict__ hbar) {
    __shared__ float4 sH[4][32];
    __shared__ float4 sD[4][32];

    const int t    = threadIdx.x;
    const int warp = t >> 5;
    const int lane = t & 31;
    const int j    = warp >> 1;       // node slot 0..3
    const int half = warp & 1;
    const int node = blockIdx.x * 4 + j;

    const int* offH = g_off + HPAIR * (N_NODES + 1);
    const int* offD = g_off + DPAIR * (N_NODES + 1);
    const int* idxH = g_eidx + eidx_base(HPAIR);
    const int* idxD = g_eidx + eidx_base(DPAIR);

    int h0 = __ldg(offH + node), h1 = __ldg(offH + node + 1);
    int d0 = __ldg(offD + node), d1 = __ldg(offD + node + 1);
    int hm = (h0 + h1 + 1) >> 1;
    int dm = (d0 + d1 + 1) >> 1;

    int ha = half ? hm : h0, hb = half ? h1 : hm;
    int da = half ? dm : d0, db = half ? d1 : dm;

    float4 pH = gather_range(hbar, idxH, ha, hb, lane);
    float4 pD = gather_range(g_Hd, idxD, da, db, lane);

    if (half) {
        sH[j][lane] = pH;
        sD[j][lane] = pD;
    }
    __syncthreads();
    if (!half) {
        acc_add(pH, sH[j][lane]);
        acc_add(pD, sD[j][lane]);
        float invh = 1.f / fmaxf((float)(h1 - h0), 1.f);
        float invd = 1.f / fmaxf((float)(d1 - d0), 1.f);
        float4 o;
        o.x = pH.x * invh + pD.x * invd;
        o.y = pH.y * invh + pD.y * invd;
        o.z = pH.z * invh + pD.z * invd;
        o.w = pH.w * invh + pD.w * invd;
        *(float4*)(g_neigh + (size_t)node * D + lane * 4) = o;
    }
}

// ---------------- GEMM + bias + ReLU (identical to R5) ----------------
template <int LAYER, int DOUT, int BM, int BN, int TM, int TN, int MAXB>
__global__ void __launch_bounds__(256, MAXB)
gemm_kernel(const float* __restrict__ Hext,
            const float* __restrict__ W,
            const float* __restrict__ bias,
            float* __restrict__ outext) {
    constexpr int BK = 32, K = 2 * D, NK = K / BK;
    constexpr int TNP = TN / 2;
    constexpr int NA = (BM * BK) / (256 * 4);
    constexpr int NB = (BN * BK) / (256 * 4);
    constexpr int APAD = BM + 4;
    constexpr int BPAD = BN + 4;

    const float* H = (LAYER == 0) ? Hext : g_H1;
    float* out     = (LAYER == 0) ? g_H1 : outext;

    __shared__ float As[BK][APAD];
    __shared__ float Bs[BK][BPAD];

    const int t    = threadIdx.x;
    const int row0 = blockIdx.x * BM;
    const int tx   = t & 15;
    const int ty   = t >> 4;

    float4 pa[NA], pb[NB];

    auto load_tile = [&](int kit) {
        const int k0 = kit * BK;
        const float* Asrc = (k0 < D) ? (H + k0) : (g_neigh + (k0 - D));
#pragma unroll
        for (int v = 0; v < NA; v++) {
            int id = v * 256 + t;
            int m  = id >> 3;
            int kq = id & 7;
            int r  = min(row0 + m, N_NODES - 1);
            pa[v] = __ldg((const float4*)(Asrc + (size_t)r * D) + kq);
        }
#pragma unroll
        for (int v = 0; v < NB; v++) {
            int id = v * 256 + t;
            int n  = id >> 3;
            int kq = id & 7;
            pb[v] = (n < DOUT) ? __ldg((const float4*)(W + n * K + k0) + kq)
                               : make_float4(0.f, 0.f, 0.f, 0.f);
        }
    };
    auto store_tile = [&]() {
#pragma unroll
        for (int v = 0; v < NA; v++) {
            int id = v * 256 + t;
            int m  = id >> 3;
            int kq = id & 7;
            int col = (((m >> 2) ^ (kq >> 1)) << 2) + (m & 3);
            As[(kq << 2) + 0][col] = pa[v].x;
            As[(kq << 2) + 1][col] = pa[v].y;
            As[(kq << 2) + 2][col] = pa[v].z;
            As[(kq << 2) + 3][col] = pa[v].w;
        }
#pragma unroll
        for (int v = 0; v < NB; v++) {
            int id = v * 256 + t;
            int n  = id >> 3;
            int kq = id & 7;
            int col = (((n >> 2) ^ (kq >> 1)) << 2) + (n & 3);
            Bs[(kq << 2) + 0][col] = pb[v].x;
            Bs[(kq << 2) + 1][col] = pb[v].y;
            Bs[(kq << 2) + 2][col] = pb[v].z;
            Bs[(kq << 2) + 3][col] = pb[v].w;
        }
    };

    ull acc2[TM][TNP];
#pragma unroll
    for (int i = 0; i < TM; i++)
#pragma unroll
        for (int p = 0; p < TNP; p++) acc2[i][p] = 0ULL;

    load_tile(0);

    for (int kit = 0; kit < NK; kit++) {
        store_tile();
        __syncthreads();
        if (kit + 1 < NK) load_tile(kit + 1);

#pragma unroll
        for (int kk = 0; kk < BK; kk++) {
            const int s = (kk >> 3) & 3;
            ull ad[TM];
#pragma unroll
            for (int u = 0; u < TM / 4; u++) {
                int gA = ((TM / 4) * ty + u) ^ s;
                float4 a = *(const float4*)&As[kk][gA << 2];
                ad[4 * u + 0] = packf2(a.x, a.x);
                ad[4 * u + 1] = packf2(a.y, a.y);
                ad[4 * u + 2] = packf2(a.z, a.z);
                ad[4 * u + 3] = packf2(a.w, a.w);
            }
            ull bp[TNP];
#pragma unroll
            for (int u = 0; u < TN / 4; u++) {
                int gB = (tx * (TN / 4) + u) ^ s;
                ulonglong2 bb = *(const ulonglong2*)&Bs[kk][gB << 2];
                bp[2 * u + 0] = bb.x;
                bp[2 * u + 1] = bb.y;
            }
#pragma unroll
            for (int i = 0; i < TM; i++)
#pragma unroll
                for (int p = 0; p < TNP; p++)
                    acc2[i][p] = fma2(ad[i], bp[p], acc2[i][p]);
        }
        __syncthreads();
    }

    float bn[TN];
#pragma unroll
    for (int j = 0; j < TN; j++) {
        int n = tx * TN + j;
        bn[j] = (n < DOUT) ? __ldg(bias + n) : 0.f;
    }
#pragma unroll
    for (int i = 0; i < TM; i++) {
        int r = row0 + ty * TM + i;
        if (r >= N_NODES) continue;
        float res[TN];
#pragma unroll
        for (int p = 0; p < TNP; p++) {
            float lo, hi;
            unpackf2(acc2[i][p], lo, hi);
            res[2 * p + 0] = fmaxf(lo + bn[2 * p + 0], 0.f);
            res[2 * p + 1] = fmaxf(hi + bn[2 * p + 1], 0.f);
        }
        if (DOUT == BN) {
#pragma unroll
            for (int u = 0; u < TN / 4; u++) {
                float4 o = make_float4(res[4 * u], res[4 * u + 1],
                                       res[4 * u + 2], res[4 * u + 3]);
                *(float4*)(out + (size_t)r * DOUT + tx * TN + 4 * u) = o;
            }
        } else {
#pragma unroll
            for (int j = 0; j < TN; j++) {
                int n = tx * TN + j;
                if (n < DOUT) out[(size_t)r * DOUT + n] = res[j];
            }
        }
    }
}

// ---------------- launch ----------------
extern "C" void kernel_launch(void* const* d_in, const int* in_sizes, int n_in,
                              void* d_out, int out_size) {
    const float* x     = (const float*)d_in[0];
    const float* hbar0 = (const float*)d_in[1];
    const float* hbar1 = (const float*)d_in[2];
    const float* W0    = (const float*)d_in[3];
    const float* b0    = (const float*)d_in[4];
    const float* W1    = (const float*)d_in[5];
    const float* b1    = (const float*)d_in[6];
    const int* hsrc0   = (const int*)d_in[7];
    const int* hdst0   = (const int*)d_in[8];
    const int* ssrc0   = (const int*)d_in[9];
    const int* sdst0   = (const int*)d_in[10];
    const int* hsrc1   = (const int*)d_in[11];
    const int* hdst1   = (const int*)d_in[12];
    const int* ssrc1   = (const int*)d_in[13];
    const int* sdst1   = (const int*)d_in[14];
    float* out = (float*)d_out;

    const int GE   = (E_TOT + 255) / 256;
    const int GAGG = N_NODES / 4;                 // 12500 blocks, 4 nodes each
    const int GEL  = (N_NODES * D / 4 + 255) / 256;

    // ---- CSR build ----
    void* cnt_ptr = nullptr;
    cudaGetSymbolAddress(&cnt_ptr, g_cnt);
    cudaMemsetAsync(cnt_ptr, 0, sizeof(int) * 4 * N_NODES);
    count_all_kernel<<<GE, 256>>>(hdst0, sdst0, hdst1, sdst1);
    scan_kernel<<<4, 1024>>>();
    bucket_all_kernel<<<GE, 256>>>(hsrc0, hdst0, ssrc0, sdst0,
                                   hsrc1, hdst1, ssrc1, sdst1);

    // ---- layer 0 ----
    hdelta_kernel<0><<<GEL, 256>>>(x, hbar0);
    agg_split_kernel<0, 1><<<GAGG, 256>>>(hbar0);
    gemm_kernel<0, 128, 128, 128, 8, 8, 2><<<(N_NODES + 127) / 128, 256>>>(x, W0, b0, nullptr);

    // ---- layer 1 ----
    hdelta_kernel<1><<<GEL, 256>>>(nullptr, hbar1);
    agg_split_kernel<2, 3><<<GAGG, 256>>>(hbar1);
    gemm_kernel<1, NCLS, 64, 64, 4, 4, 3><<<(N_NODES + 63) / 64, 256>>>(nullptr, W1, b1, out);
}

// round 9
// speedup vs baseline: 1.2084x; 1.1068x over previous
#include <cuda_runtime.h>
#include <stdint.h>

#define N_NODES 50000
#define D       128
#define EH      500000
#define ES      250000
#define NCLS    47
#define E_TOT   (2 * (EH + ES))

typedef unsigned long long ull;

// ---------------- scratch (device globals; no runtime allocation) ----------------
__device__ int   g_cnt[4 * N_NODES];
__device__ int   g_off[4 * (N_NODES + 1)];
__device__ int   g_cur[4 * N_NODES];
__device__ int   g_eidx[E_TOT];
__device__ float g_neigh0[N_NODES * D];   // layer-0 neigh (hist+delta)
__device__ float g_neigh1[N_NODES * D];   // layer-1 neigh (hist, then +delta)
__device__ float g_H1[N_NODES * D];       // layer-0 output
__device__ float g_Hd[N_NODES * D];       // H - HBar for current layer

__device__ __forceinline__ int eidx_base(int p) {
    return p == 0 ? 0 : p == 1 ? EH : p == 2 ? (EH + ES) : (2 * EH + ES);
}

// ---------------- f32x2 packed math helpers ----------------
__device__ __forceinline__ ull fma2(ull a, ull b, ull c) {
    ull d;
    asm("fma.rn.f32x2 %0, %1, %2, %3;" : "=l"(d) : "l"(a), "l"(b), "l"(c));
    return d;
}
__device__ __forceinline__ ull packf2(float x, float y) {
    ull d;
    asm("mov.b64 %0, {%1, %2};" : "=l"(d) : "f"(x), "f"(y));
    return d;
}
__device__ __forceinline__ void unpackf2(ull v, float& x, float& y) {
    asm("mov.b64 {%0, %1}, %2;" : "=f"(x), "=f"(y) : "l"(v));
}

// ---------------- K1: count histogram  ||  hdelta0 = x - hbar0 ----------------
#define GE_BLOCKS  ((E_TOT + 255) / 256)          // 5860
#define GEL_BLOCKS ((N_NODES * D / 4 + 255) / 256) // 6250

__global__ void count_hdelta0_kernel(const int* __restrict__ hd0, const int* __restrict__ sd0,
                                     const int* __restrict__ hd1, const int* __restrict__ sd1,
                                     const float* __restrict__ x, const float* __restrict__ hbar0) {
    int b = blockIdx.x;
    if (b < GE_BLOCKS) {
        int i = b * blockDim.x + threadIdx.x;
        if (i >= E_TOT) return;
        int pair, off;
        const int* p;
        if (i < EH)               { pair = 0; p = hd0; off = i; }
        else if (i < EH + ES)     { pair = 1; p = sd0; off = i - EH; }
        else if (i < 2 * EH + ES) { pair = 2; p = hd1; off = i - EH - ES; }
        else                      { pair = 3; p = sd1; off = i - 2 * EH - ES; }
        atomicAdd(&g_cnt[pair * N_NODES + __ldg(p + off)], 1);
    } else {
        int i = (b - GE_BLOCKS) * blockDim.x + threadIdx.x;
        if (i >= N_NODES * D / 4) return;
        float4 a = __ldg((const float4*)x + i);
        float4 h = __ldg((const float4*)hbar0 + i);
        ((float4*)g_Hd)[i] = make_float4(a.x - h.x, a.y - h.y, a.z - h.z, a.w - h.w);
    }
}

// ---------------- scan (4 blocks, one per pair) ----------------
__global__ void scan_kernel() {
    const int p = blockIdx.x;
    int* cnt = g_cnt + p * N_NODES;
    int* off = g_off + p * (N_NODES + 1);
    int* cur = g_cur + p * N_NODES;
    const int T = 1024;
    const int C = (N_NODES + T - 1) / T;
    __shared__ int part[T];
    int t = threadIdx.x;
    int base = t * C;
    int s = 0;
#pragma unroll 1
    for (int i = 0; i < C; i++) {
        int j = base + i;
        if (j < N_NODES) s += cnt[j];
    }
    part[t] = s;
    __syncthreads();
    for (int d2 = 1; d2 < T; d2 <<= 1) {
        int v = (t >= d2) ? part[t - d2] : 0;
        __syncthreads();
        part[t] += v;
        __syncthreads();
    }
    int run = part[t] - s;
#pragma unroll 1
    for (int i = 0; i < C; i++) {
        int j = base + i;
        if (j < N_NODES) {
            off[j] = run;
            cur[j] = run;
            run += cnt[j];
        }
    }
    if (t == T - 1) off[N_NODES] = part[t];
}

__global__ void bucket_all_kernel(const int* __restrict__ hs0, const int* __restrict__ hd0,
                                  const int* __restrict__ ss0, const int* __restrict__ sd0,
                                  const int* __restrict__ hs1, const int* __restrict__ hd1,
                                  const int* __restrict__ ss1, const int* __restrict__ sd1) {
    int i = blockIdx.x * blockDim.x + threadIdx.x;
    if (i >= E_TOT) return;
    int pair, off;
    const int *ps, *pd;
    if (i < EH)               { pair = 0; ps = hs0; pd = hd0; off = i; }
    else if (i < EH + ES)     { pair = 1; ps = ss0; pd = sd0; off = i - EH; }
    else if (i < 2 * EH + ES) { pair = 2; ps = hs1; pd = hd1; off = i - EH - ES; }
    else                      { pair = 3; ps = ss1; pd = sd1; off = i - 2 * EH - ES; }
    int d = __ldg(pd + off);
    int pos = atomicAdd(&g_cur[pair * N_NODES + d], 1);
    g_eidx[eidx_base(pair) + pos] = __ldg(ps + off);
}

// ---------------- gather primitives (warp-collective, MLP=4) ----------------
__device__ __forceinline__ void acc_add(float4& a, float4 v) {
    a.x += v.x; a.y += v.y; a.z += v.z; a.w += v.w;
}

__device__ __forceinline__ float4 gather_mean(const float* __restrict__ feat,
                                              const int* __restrict__ idx,
                                              int e0, int e1, int lane) {
    float4 a0 = make_float4(0,0,0,0), a1 = a0, a2 = a0, a3 = a0;
    int e = e0;
    for (; e + 4 <= e1; e += 4) {
        int i0 = __ldg(idx + e + 0), i1 = __ldg(idx + e + 1);
        int i2 = __ldg(idx + e + 2), i3 = __ldg(idx + e + 3);
        float4 v0 = __ldg((const float4*)(feat + (size_t)i0 * D) + lane);
        float4 v1 = __ldg((const float4*)(feat + (size_t)i1 * D) + lane);
        float4 v2 = __ldg((const float4*)(feat + (size_t)i2 * D) + lane);
        float4 v3 = __ldg((const float4*)(feat + (size_t)i3 * D) + lane);
        acc_add(a0, v0); acc_add(a1, v1); acc_add(a2, v2); acc_add(a3, v3);
    }
    for (; e < e1; e++) {
        int s = __ldg(idx + e);
        acc_add(a0, __ldg((const float4*)(feat + (size_t)s * D) + lane));
    }
    acc_add(a0, a1); acc_add(a2, a3); acc_add(a0, a2);
    float inv = 1.f / fmaxf((float)(e1 - e0), 1.f);
    return make_float4(a0.x * inv, a0.y * inv, a0.z * inv, a0.w * inv);
}

// ---------------- K4: agg0 (pairs 0,1 -> g_neigh0)  ||  agg1_hist (pair 2 -> g_neigh1) ----
#define GAGG_BLOCKS ((N_NODES * 32 + 255) / 256)   // 6250

__global__ void agg_combined_kernel(const float* __restrict__ hbar0,
                                    const float* __restrict__ hbar1) {
    int b = blockIdx.x;
    if (b < GAGG_BLOCKS) {
        // ---- layer-0 full aggregation ----
        int g = b * blockDim.x + threadIdx.x;
        int w = g >> 5, lane = g & 31;
        if (w >= N_NODES) return;
        const int* offH = g_off + 0 * (N_NODES + 1);
        const int* offD = g_off + 1 * (N_NODES + 1);
        int h0 = __ldg(offH + w), h1 = __ldg(offH + w + 1);
        int d0 = __ldg(offD + w), d1 = __ldg(offD + w + 1);
        float4 o = gather_mean(hbar0, g_eidx + eidx_base(0), h0, h1, lane);
        float4 dm = gather_mean(g_Hd,  g_eidx + eidx_base(1), d0, d1, lane);
        o.x += dm.x; o.y += dm.y; o.z += dm.z; o.w += dm.w;
        *(float4*)(g_neigh0 + (size_t)w * D + lane * 4) = o;
    } else {
        // ---- layer-1 hist-only aggregation ----
        int g = (b - GAGG_BLOCKS) * blockDim.x + threadIdx.x;
        int w = g >> 5, lane = g & 31;
        if (w >= N_NODES) return;
        const int* offH = g_off + 2 * (N_NODES + 1);
        int h0 = __ldg(offH + w), h1 = __ldg(offH + w + 1);
        float4 o = gather_mean(hbar1, g_eidx + eidx_base(2), h0, h1, lane);
        *(float4*)(g_neigh1 + (size_t)w * D + lane * 4) = o;
    }
}

// ---------------- agg1_delta: g_neigh1 += mean over pair 3 of g_Hd ----------------
__global__ void agg1_delta_kernel() {
    int g = blockIdx.x * blockDim.x + threadIdx.x;
    int w = g >> 5, lane = g & 31;
    if (w >= N_NODES) return;
    const int* offD = g_off + 3 * (N_NODES + 1);
    int d0 = __ldg(offD + w), d1 = __ldg(offD + w + 1);
    if (d0 == d1) return;
    float4 dm = gather_mean(g_Hd, g_eidx + eidx_base(3), d0, d1, lane);
    float4* dst = (float4*)(g_neigh1 + (size_t)w * D + lane * 4);
    float4 o = *dst;
    o.x += dm.x; o.y += dm.y; o.z += dm.z; o.w += dm.w;
    *dst = o;
}

// ---------------- GEMM + bias + ReLU  (layer0 epilogue also writes g_Hd) ----------------
template <int LAYER, int DOUT, int BM, int BN, int TM, int TN, int MAXB>
__global__ void __launch_bounds__(256, MAXB)
gemm_kernel(const float* __restrict__ Hext,
            const float* __restrict__ W,
            const float* __restrict__ bias,
            const float* __restrict__ hbar1,   // layer0 only: for fused hdelta1
            float* __restrict__ outext) {
    constexpr int BK = 32, K = 2 * D, NK = K / BK;
    constexpr int TNP = TN / 2;
    constexpr int NA = (BM * BK) / (256 * 4);
    constexpr int NB = (BN * BK) / (256 * 4);
    constexpr int APAD = BM + 4;
    constexpr int BPAD = BN + 4;

    const float* H     = (LAYER == 0) ? Hext     : g_H1;
    const float* neigh = (LAYER == 0) ? g_neigh0 : g_neigh1;
    float* out         = (LAYER == 0) ? g_H1     : outext;

    __shared__ float As[BK][APAD];
    __shared__ float Bs[BK][BPAD];

    const int t    = threadIdx.x;
    const int row0 = blockIdx.x * BM;
    const int tx   = t & 15;
    const int ty   = t >> 4;

    float4 pa[NA], pb[NB];

    auto load_tile = [&](int kit) {
        const int k0 = kit * BK;
        const float* Asrc = (k0 < D) ? (H + k0) : (neigh + (k0 - D));
#pragma unroll
        for (int v = 0; v < NA; v++) {
            int id = v * 256 + t;
            int m  = id >> 3;
            int kq = id & 7;
            int r  = min(row0 + m, N_NODES - 1);
            pa[v] = __ldg((const float4*)(Asrc + (size_t)r * D) + kq);
        }
#pragma unroll
        for (int v = 0; v < NB; v++) {
            int id = v * 256 + t;
            int n  = id >> 3;
            int kq = id & 7;
            pb[v] = (n < DOUT) ? __ldg((const float4*)(W + n * K + k0) + kq)
                               : make_float4(0.f, 0.f, 0.f, 0.f);
        }
    };
    auto store_tile = [&]() {
#pragma unroll
        for (int v = 0; v < NA; v++) {
            int id = v * 256 + t;
            int m  = id >> 3;
            int kq = id & 7;
            int col = (((m >> 2) ^ (kq >> 1)) << 2) + (m & 3);
            As[(kq << 2) + 0][col] = pa[v].x;
            As[(kq << 2) + 1][col] = pa[v].y;
            As[(kq << 2) + 2][col] = pa[v].z;
            As[(kq << 2) + 3][col] = pa[v].w;
        }
#pragma unroll
        for (int v = 0; v < NB; v++) {
            int id = v * 256 + t;
            int n  = id >> 3;
            int kq = id & 7;
            int col = (((n >> 2) ^ (kq >> 1)) << 2) + (n & 3);
            Bs[(kq << 2) + 0][col] = pb[v].x;
            Bs[(kq << 2) + 1][col] = pb[v].y;
            Bs[(kq << 2) + 2][col] = pb[v].z;
            Bs[(kq << 2) + 3][col] = pb[v].w;
        }
    };

    ull acc2[TM][TNP];
#pragma unroll
    for (int i = 0; i < TM; i++)
#pragma unroll
        for (int p = 0; p < TNP; p++) acc2[i][p] = 0ULL;

    load_tile(0);

    for (int kit = 0; kit < NK; kit++) {
        store_tile();
        __syncthreads();
        if (kit + 1 < NK) load_tile(kit + 1);

#pragma unroll
        for (int kk = 0; kk < BK; kk++) {
            const int s = (kk >> 3) & 3;
            ull ad[TM];
#pragma unroll
            for (int u = 0; u < TM / 4; u++) {
                int gA = ((TM / 4) * ty + u) ^ s;
                float4 a = *(const float4*)&As[kk][gA << 2];
                ad[4 * u + 0] = packf2(a.x, a.x);
                ad[4 * u + 1] = packf2(a.y, a.y);
                ad[4 * u + 2] = packf2(a.z, a.z);
                ad[4 * u + 3] = packf2(a.w, a.w);
            }
            ull bp[TNP];
#pragma unroll
            for (int u = 0; u < TN / 4; u++) {
                int gB = (tx * (TN / 4) + u) ^ s;
                ulonglong2 bb = *(const ulonglong2*)&Bs[kk][gB << 2];
                bp[2 * u + 0] = bb.x;
                bp[2 * u + 1] = bb.y;
            }
#pragma unroll
            for (int i = 0; i < TM; i++)
#pragma unroll
                for (int p = 0; p < TNP; p++)
                    acc2[i][p] = fma2(ad[i], bp[p], acc2[i][p]);
        }
        __syncthreads();
    }

    float bn[TN];
#pragma unroll
    for (int j = 0; j < TN; j++) {
        int n = tx * TN + j;
        bn[j] = (n < DOUT) ? __ldg(bias + n) : 0.f;
    }
#pragma unroll
    for (int i = 0; i < TM; i++) {
        int r = row0 + ty * TM + i;
        if (r >= N_NODES) continue;
        float res[TN];
#pragma unroll
        for (int p = 0; p < TNP; p++) {
            float lo, hi;
            unpackf2(acc2[i][p], lo, hi);
            res[2 * p + 0] = fmaxf(lo + bn[2 * p + 0], 0.f);
            res[2 * p + 1] = fmaxf(hi + bn[2 * p + 1], 0.f);
        }
        if (LAYER == 0) {
            // dense store + fused hdelta1: g_Hd = relu_out - hbar1
#pragma unroll
            for (int u = 0; u < TN / 4; u++) {
                int n = tx * TN + 4 * u;
                float4 o = make_float4(res[4 * u], res[4 * u + 1],
                                       res[4 * u + 2], res[4 * u + 3]);
                *(float4*)(out + (size_t)r * DOUT + n) = o;
                float4 hb = __ldg((const float4*)(hbar1 + (size_t)r * D + n));
                float4 hd = make_float4(o.x - hb.x, o.y - hb.y, o.z - hb.z, o.w - hb.w);
                *(float4*)(g_Hd + (size_t)r * D + n) = hd;
            }
        } else {
#pragma unroll
            for (int j = 0; j < TN; j++) {
                int n = tx * TN + j;
                if (n < DOUT) out[(size_t)r * DOUT + n] = res[j];
            }
        }
    }
}

// ---------------- launch ----------------
extern "C" void kernel_launch(void* const* d_in, const int* in_sizes, int n_in,
                              void* d_out, int out_size) {
    const float* x     = (const float*)d_in[0];
    const float* hbar0 = (const float*)d_in[1];
    const float* hbar1 = (const float*)d_in[2];
    const float* W0    = (const float*)d_in[3];
    const float* b0    = (const float*)d_in[4];
    const float* W1    = (const float*)d_in[5];
    const float* b1    = (const float*)d_in[6];
    const int* hsrc0   = (const int*)d_in[7];
    const int* hdst0   = (const int*)d_in[8];
    const int* ssrc0   = (const int*)d_in[9];
    const int* sdst0   = (const int*)d_in[10];
    const int* hsrc1   = (const int*)d_in[11];
    const int* hdst1   = (const int*)d_in[12];
    const int* ssrc1   = (const int*)d_in[13];
    const int* sdst1   = (const int*)d_in[14];
    float* out = (float*)d_out;

    // ---- K0: zero counters ----
    void* cnt_ptr = nullptr;
    cudaGetSymbolAddress(&cnt_ptr, g_cnt);
    cudaMemsetAsync(cnt_ptr, 0, sizeof(int) * 4 * N_NODES);

    // ---- K1: count || hdelta0 ----
    count_hdelta0_kernel<<<GE_BLOCKS + GEL_BLOCKS, 256>>>(hdst0, sdst0, hdst1, sdst1, x, hbar0);

    // ---- K2/K3: scan + bucket ----
    scan_kernel<<<4, 1024>>>();
    bucket_all_kernel<<<GE_BLOCKS, 256>>>(hsrc0, hdst0, ssrc0, sdst0,
                                          hsrc1, hdst1, ssrc1, sdst1);

    // ---- K4: agg0 || agg1_hist ----
    agg_combined_kernel<<<2 * GAGG_BLOCKS, 256>>>(hbar0, hbar1);

    // ---- K5: gemm0 (+ fused hdelta1 epilogue) ----
    gemm_kernel<0, 128, 128, 128, 8, 8, 2><<<(N_NODES + 127) / 128, 256>>>(x, W0, b0, hbar1, nullptr);

    // ---- K6: agg1_delta ----
    agg1_delta_kernel<<<GAGG_BLOCKS, 256>>>();

    // ---- K7: gemm1 ----
    gemm_kernel<1, NCLS, 64, 64, 4, 4, 3><<<(N_NODES + 63) / 64, 256>>>(nullptr, W1, b1, nullptr, out);
}